// round 1
// baseline (speedup 1.0000x reference)
#include <cuda_runtime.h>
#include <math.h>

// Problem constants
#define B_    2
#define S_    2048
#define V_    1024
#define D_    512
#define H_    8
#define L_    6
#define DFF_  2048
#define DK_   64
#define M_    (B_*S_)        // 4096 token rows

// ---------------------------------------------------------------------------
// Scratch (device globals: allocation-free per harness rules)
// ---------------------------------------------------------------------------
__device__ float g_x [M_*D_];
__device__ float g_h [M_*D_];
__device__ float g_q [M_*D_];
__device__ float g_k [M_*D_];
__device__ float g_v [M_*D_];
__device__ float g_o [M_*D_];
__device__ float g_ff[M_*DFF_];

// ---------------------------------------------------------------------------
// Embedding + sinusoidal positional encoding
// ---------------------------------------------------------------------------
__global__ void embed_kernel(const int* __restrict__ ids,
                             const float* __restrict__ emb,
                             float* __restrict__ x) {
    int row = blockIdx.x;                 // 0..M_-1
    int s   = row & (S_ - 1);             // position within sequence
    int id  = ids[row];
    const float* e = emb + (size_t)id * D_;
    float* xr = x + (size_t)row * D_;
    const float coef = -9.210340371976184f / (float)D_;  // -ln(10000)/D
    for (int d = threadIdx.x; d < D_; d += blockDim.x) {
        int d2 = d & ~1;
        float div = expf((float)d2 * coef);
        float ang = (float)s * div;
        float pe  = (d & 1) ? cosf(ang) : sinf(ang);
        xr[d] = e[d] + pe;
    }
}

// ---------------------------------------------------------------------------
// LayerNorm: one block per row of 512
// ---------------------------------------------------------------------------
__global__ void ln_kernel(const float* __restrict__ x,
                          const float* __restrict__ w,
                          const float* __restrict__ b,
                          float* __restrict__ out) {
    __shared__ float red[4];
    int row = blockIdx.x;
    int tid = threadIdx.x;                // 128 threads
    const float* xr = x + (size_t)row * D_;
    float v[4];
#pragma unroll
    for (int i = 0; i < 4; i++) v[i] = xr[tid + 128 * i];

    float s = v[0] + v[1] + v[2] + v[3];
#pragma unroll
    for (int o = 16; o; o >>= 1) s += __shfl_xor_sync(0xffffffffu, s, o);
    if ((tid & 31) == 0) red[tid >> 5] = s;
    __syncthreads();
    float mu = (red[0] + red[1] + red[2] + red[3]) * (1.0f / D_);

    float d2 = 0.f;
#pragma unroll
    for (int i = 0; i < 4; i++) { float t = v[i] - mu; d2 += t * t; }
#pragma unroll
    for (int o = 16; o; o >>= 1) d2 += __shfl_xor_sync(0xffffffffu, d2, o);
    __syncthreads();                       // everyone done reading red
    if ((tid & 31) == 0) red[tid >> 5] = d2;
    __syncthreads();
    float var  = (red[0] + red[1] + red[2] + red[3]) * (1.0f / D_);
    float rstd = rsqrtf(var + 1e-5f);

    float* orow = out + (size_t)row * D_;
#pragma unroll
    for (int i = 0; i < 4; i++) {
        int d = tid + 128 * i;
        orow[d] = (v[i] - mu) * rstd * w[d] + b[d];
    }
}

// ---------------------------------------------------------------------------
// Tiled fp32 GEMM: C[M,N] = A[M,K] @ W[K,N] + bias  (+ epilogue)
// OP: 0 = bias only, 1 = bias+ReLU, 2 = bias+residual add
// BM=128, BN=64, BK=16, 256 threads, 8x4 per-thread microtile
// ---------------------------------------------------------------------------
template<int OP>
__global__ void gemm_kernel(const float* __restrict__ A,
                            const float* __restrict__ Bw,
                            const float* __restrict__ bias,
                            const float* __restrict__ res,
                            float* __restrict__ C,
                            int M, int N, int K) {
    __shared__ float As[16][128];
    __shared__ float Bs[16][64];

    int tid = threadIdx.x;
    int tx = tid & 15;       // N dir (x4)
    int ty = tid >> 4;       // M dir (x8)
    int bx = blockIdx.x;     // N tile
    int by = blockIdx.y;     // M tile

    const float* Ab = A  + (size_t)by * 128 * K;
    const float* Bb = Bw + (size_t)bx * 64;

    float acc[8][4];
#pragma unroll
    for (int i = 0; i < 8; i++)
#pragma unroll
        for (int j = 0; j < 4; j++) acc[i][j] = 0.f;

    for (int k0 = 0; k0 < K; k0 += 16) {
        // A tile: 128x16, 512 float4s, 2 per thread
#pragma unroll
        for (int t = 0; t < 2; t++) {
            int li = tid + t * 256;
            int r  = li >> 2;
            int c4 = (li & 3) << 2;
            float4 av = *(const float4*)(Ab + (size_t)r * K + k0 + c4);
            As[c4 + 0][r] = av.x;
            As[c4 + 1][r] = av.y;
            As[c4 + 2][r] = av.z;
            As[c4 + 3][r] = av.w;
        }
        // B tile: 16x64, 256 float4s, 1 per thread
        {
            int r  = tid >> 4;
            int c4 = (tid & 15) << 2;
            *(float4*)(&Bs[r][c4]) = *(const float4*)(Bb + (size_t)(k0 + r) * N + c4);
        }
        __syncthreads();

#pragma unroll
        for (int kk = 0; kk < 16; kk++) {
            float4 a0 = *(const float4*)(&As[kk][ty * 8]);
            float4 a1 = *(const float4*)(&As[kk][ty * 8 + 4]);
            float4 b0 = *(const float4*)(&Bs[kk][tx * 4]);
            float ar[8] = {a0.x, a0.y, a0.z, a0.w, a1.x, a1.y, a1.z, a1.w};
            float br[4] = {b0.x, b0.y, b0.z, b0.w};
#pragma unroll
            for (int i = 0; i < 8; i++)
#pragma unroll
                for (int j = 0; j < 4; j++)
                    acc[i][j] = fmaf(ar[i], br[j], acc[i][j]);
        }
        __syncthreads();
    }

    int ccol = bx * 64 + tx * 4;
    float4 bv = *(const float4*)(bias + ccol);
#pragma unroll
    for (int i = 0; i < 8; i++) {
        int r = by * 128 + ty * 8 + i;
        float4 cv;
        cv.x = acc[i][0] + bv.x;
        cv.y = acc[i][1] + bv.y;
        cv.z = acc[i][2] + bv.z;
        cv.w = acc[i][3] + bv.w;
        if (OP == 1) {
            cv.x = fmaxf(cv.x, 0.f); cv.y = fmaxf(cv.y, 0.f);
            cv.z = fmaxf(cv.z, 0.f); cv.w = fmaxf(cv.w, 0.f);
        }
        if (OP == 2) {
            float4 rv = *(const float4*)(res + (size_t)r * N + ccol);
            cv.x += rv.x; cv.y += rv.y; cv.z += rv.z; cv.w += rv.w;
        }
        *(float4*)(C + (size_t)r * N + ccol) = cv;
    }
}

// ---------------------------------------------------------------------------
// Flash attention (causal + pad mask), fp32, DK=64
// Block = (q-tile 64 rows, head, batch). 256 threads = 64 rows x 4-lane quads.
// Shared tiles padded to stride 68 for conflict-free access.
// ---------------------------------------------------------------------------
#define SP 68
#define FLASH_SMEM ((4 * 64 * SP + 64) * (int)sizeof(float))

__global__ void flash_kernel(const float* __restrict__ Q,
                             const float* __restrict__ K,
                             const float* __restrict__ V,
                             const int* __restrict__ ids,
                             float* __restrict__ O) {
    extern __shared__ float sm[];
    float* Qs    = sm;
    float* Ks    = Qs + 64 * SP;
    float* Vs    = Ks + 64 * SP;
    float* Ps    = Vs + 64 * SP;
    float* kbias = Ps + 64 * SP;   // 64 entries: 0 or -1e30 (pad mask)

    int qt = blockIdx.x;
    int h  = blockIdx.y;
    int b  = blockIdx.z;
    int q0 = qt * 64;
    int tid = threadIdx.x;
    int i = tid >> 2;              // query row within tile (0..63)
    int g = tid & 3;               // quad lane

    size_t base = ((size_t)b * S_) * D_ + (size_t)h * DK_;
    const int* idrow = ids + b * S_;
    const float scale = 0.125f;    // 1/sqrt(64)

    // Load Q tile (64x64) once
#pragma unroll
    for (int t = 0; t < 4; t++) {
        int li = tid + t * 256;
        int r  = li >> 4;
        int c4 = (li & 15) << 2;
        *(float4*)(Qs + r * SP + c4) =
            *(const float4*)(Q + base + (size_t)(q0 + r) * D_ + c4);
    }

    float m = -1e30f, lsum = 0.f;
    float o[16];
#pragma unroll
    for (int d = 0; d < 16; d++) o[d] = 0.f;

    for (int k0 = 0; k0 <= q0; k0 += 64) {
        // Load K, V tiles
#pragma unroll
        for (int t = 0; t < 4; t++) {
            int li = tid + t * 256;
            int r  = li >> 4;
            int c4 = (li & 15) << 2;
            *(float4*)(Ks + r * SP + c4) =
                *(const float4*)(K + base + (size_t)(k0 + r) * D_ + c4);
            *(float4*)(Vs + r * SP + c4) =
                *(const float4*)(V + base + (size_t)(k0 + r) * D_ + c4);
        }
        if (tid < 64) kbias[tid] = (idrow[k0 + tid] != 0) ? 0.f : -1e30f;
        __syncthreads();

        // Scores: this thread handles row i, keys j = g + 4*jj
        float sc[16];
        float rowmax = -1e30f;
#pragma unroll
        for (int jj = 0; jj < 16; jj++) {
            int j = g + (jj << 2);
            float s = 0.f;
            const float* qr = Qs + i * SP;
            const float* kr = Ks + j * SP;
#pragma unroll
            for (int d = 0; d < 64; d++) s = fmaf(qr[d], kr[d], s);
            s = s * scale + kbias[j];
            if (k0 + j > q0 + i) s = -1e30f;   // causal
            sc[jj] = s;
            rowmax = fmaxf(rowmax, s);
        }
        rowmax = fmaxf(rowmax, __shfl_xor_sync(0xffffffffu, rowmax, 1));
        rowmax = fmaxf(rowmax, __shfl_xor_sync(0xffffffffu, rowmax, 2));

        float mnew = fmaxf(m, rowmax);
        float corr = __expf(m - mnew);
        float psum = 0.f;
#pragma unroll
        for (int jj = 0; jj < 16; jj++) {
            float p = __expf(sc[jj] - mnew);
            Ps[i * SP + g + (jj << 2)] = p;
            psum += p;
        }
        psum += __shfl_xor_sync(0xffffffffu, psum, 1);
        psum += __shfl_xor_sync(0xffffffffu, psum, 2);
        lsum = lsum * corr + psum;
        m = mnew;
        __syncwarp();   // Ps exchange within the quad (same warp)

#pragma unroll
        for (int d = 0; d < 16; d++) o[d] *= corr;
#pragma unroll
        for (int j = 0; j < 64; j++) {
            float p = Ps[i * SP + j];
            const float* vr = Vs + j * SP;
#pragma unroll
            for (int d = 0; d < 16; d++)
                o[d] = fmaf(p, vr[g + (d << 2)], o[d]);
        }
        __syncthreads();  // before next tile overwrites Ks/Vs/Ps
    }

    float inv = 1.f / lsum;
    float* orow = O + base + (size_t)(q0 + i) * D_;
#pragma unroll
    for (int d = 0; d < 16; d++)
        orow[g + (d << 2)] = o[d] * inv;
}

// ---------------------------------------------------------------------------
// Host orchestration (graph-capturable: kernel launches only)
// ---------------------------------------------------------------------------
extern "C" void kernel_launch(void* const* d_in, const int* in_sizes, int n_in,
                              void* d_out, int out_size) {
    (void)in_sizes; (void)n_in; (void)out_size;
    const int*   ids  = (const int*)  d_in[0];
    const float* emb  = (const float*)d_in[1];
    const float* wq   = (const float*)d_in[2];
    const float* bq   = (const float*)d_in[3];
    const float* wk   = (const float*)d_in[4];
    const float* bk   = (const float*)d_in[5];
    const float* wv   = (const float*)d_in[6];
    const float* bv   = (const float*)d_in[7];
    const float* wo   = (const float*)d_in[8];
    const float* bo   = (const float*)d_in[9];
    const float* ln1w = (const float*)d_in[10];
    const float* ln1b = (const float*)d_in[11];
    const float* ln2w = (const float*)d_in[12];
    const float* ln2b = (const float*)d_in[13];
    const float* w1   = (const float*)d_in[14];
    const float* b1   = (const float*)d_in[15];
    const float* w2   = (const float*)d_in[16];
    const float* b2   = (const float*)d_in[17];
    const float* outw = (const float*)d_in[18];
    const float* outb = (const float*)d_in[19];
    float* logits = (float*)d_out;

    float *x, *h, *q, *k, *v, *o, *ff;
    cudaGetSymbolAddress((void**)&x,  g_x);
    cudaGetSymbolAddress((void**)&h,  g_h);
    cudaGetSymbolAddress((void**)&q,  g_q);
    cudaGetSymbolAddress((void**)&k,  g_k);
    cudaGetSymbolAddress((void**)&v,  g_v);
    cudaGetSymbolAddress((void**)&o,  g_o);
    cudaGetSymbolAddress((void**)&ff, g_ff);

    cudaFuncSetAttribute(flash_kernel,
                         cudaFuncAttributeMaxDynamicSharedMemorySize, FLASH_SMEM);

    embed_kernel<<<M_, 128>>>(ids, emb, x);

    dim3 gD(D_ / 64,   M_ / 128);   // N=512
    dim3 gF(DFF_ / 64, M_ / 128);   // N=2048
    dim3 gV(V_ / 64,   M_ / 128);   // N=1024
    dim3 gAtt(S_ / 64, H_, B_);

    for (int l = 0; l < L_; l++) {
        const size_t oDD  = (size_t)l * D_ * D_;
        const size_t oDF  = (size_t)l * D_ * DFF_;
        const size_t oFD  = (size_t)l * DFF_ * D_;

        ln_kernel<<<M_, 128>>>(x, ln1w + l * D_, ln1b + l * D_, h);
        gemm_kernel<0><<<gD, 256>>>(h, wq + oDD, bq + l * D_, nullptr, q, M_, D_, D_);
        gemm_kernel<0><<<gD, 256>>>(h, wk + oDD, bk + l * D_, nullptr, k, M_, D_, D_);
        gemm_kernel<0><<<gD, 256>>>(h, wv + oDD, bv + l * D_, nullptr, v, M_, D_, D_);

        flash_kernel<<<gAtt, 256, FLASH_SMEM>>>(q, k, v, ids, o);

        // x = o @ wo + bo  (no residual — faithful to reference)
        gemm_kernel<0><<<gD, 256>>>(o, wo + oDD, bo + l * D_, nullptr, x, M_, D_, D_);

        ln_kernel<<<M_, 128>>>(x, ln2w + l * D_, ln2b + l * D_, h);
        gemm_kernel<1><<<gF, 256>>>(h, w1 + oDF, b1 + l * DFF_, nullptr, ff, M_, DFF_, D_);
        // x = x + ff @ w2 + b2  (in-place residual: each element touched by one thread)
        gemm_kernel<2><<<gD, 256>>>(ff, w2 + oFD, b2 + l * D_, x, x, M_, D_, DFF_);
    }

    gemm_kernel<0><<<gV, 256>>>(x, outw, outb, nullptr, logits, M_, V_, D_);
}

// round 16
// speedup vs baseline: 1.3666x; 1.3666x over previous
#include <cuda_runtime.h>
#include <cuda_bf16.h>
#include <math.h>
#include <stdint.h>

// Problem constants
#define B_    2
#define S_    2048
#define V_    1024
#define D_    512
#define H_    8
#define L_    6
#define DFF_  2048
#define DK_   64
#define M_    (B_*S_)        // 4096 token rows

#define DD    (D_*D_)        // 262144
#define DF    (D_*DFF_)      // 1048576

// Transposed/split weight offsets (element offsets into g_wT_hi / g_wT_lo)
#define OFF_WQ 0
#define OFF_WK (OFF_WQ + L_*DD)
#define OFF_WV (OFF_WK + L_*DD)
#define OFF_WO (OFF_WV + L_*DD)
#define OFF_W1 (OFF_WO + L_*DD)
#define OFF_W2 (OFF_W1 + L_*DF)
#define OFF_OW (OFF_W2 + L_*DF)
#define WT_TOTAL (OFF_OW + D_*V_)

// ---------------------------------------------------------------------------
// Scratch (device globals: allocation-free per harness rules)
// ---------------------------------------------------------------------------
__device__ float g_x[M_*D_];
__device__ float g_q[M_*D_];
__device__ float g_k[M_*D_];
__device__ float g_v[M_*D_];

__device__ __nv_bfloat16 g_h_hi[M_*D_];
__device__ __nv_bfloat16 g_h_lo[M_*D_];
__device__ __nv_bfloat16 g_o_hi[M_*D_];
__device__ __nv_bfloat16 g_o_lo[M_*D_];
__device__ __nv_bfloat16 g_x_hi[M_*D_];
__device__ __nv_bfloat16 g_x_lo[M_*D_];
__device__ __nv_bfloat16 g_ff_hi[M_*DFF_];
__device__ __nv_bfloat16 g_ff_lo[M_*DFF_];

__device__ __nv_bfloat16 g_wT_hi[WT_TOTAL];
__device__ __nv_bfloat16 g_wT_lo[WT_TOTAL];

// ---------------------------------------------------------------------------
// PTX helpers (baseline sm_80-class instructions — compile for sm_103)
// ---------------------------------------------------------------------------
__device__ __forceinline__ uint32_t smem_u32(const void* p) {
    uint32_t a;
    asm("{ .reg .u64 t; cvta.to.shared.u64 t, %1; cvt.u32.u64 %0, t; }"
        : "=r"(a) : "l"(p));
    return a;
}
__device__ __forceinline__ void ldsm4(uint32_t& r0, uint32_t& r1,
                                      uint32_t& r2, uint32_t& r3, uint32_t a) {
    asm volatile("ldmatrix.sync.aligned.m8n8.x4.shared.b16 {%0,%1,%2,%3}, [%4];"
        : "=r"(r0), "=r"(r1), "=r"(r2), "=r"(r3) : "r"(a));
}
__device__ __forceinline__ void mma16816(float* d, uint32_t a0, uint32_t a1,
                                         uint32_t a2, uint32_t a3,
                                         uint32_t b0, uint32_t b1) {
    asm volatile("mma.sync.aligned.m16n8k16.row.col.f32.bf16.bf16.f32 "
        "{%0,%1,%2,%3}, {%4,%5,%6,%7}, {%8,%9}, {%0,%1,%2,%3};"
        : "+f"(d[0]), "+f"(d[1]), "+f"(d[2]), "+f"(d[3])
        : "r"(a0), "r"(a1), "r"(a2), "r"(a3), "r"(b0), "r"(b1));
}

// ---------------------------------------------------------------------------
// Weight prep: transpose fp32 W[K,N] -> bf16 hi/lo [N,K]
// ---------------------------------------------------------------------------
__global__ void prep_w(const float* __restrict__ W, int K, int N,
                       __nv_bfloat16* __restrict__ hi, __nv_bfloat16* __restrict__ lo) {
    __shared__ float t[32][33];
    int n0 = blockIdx.x * 32, k0 = blockIdx.y * 32;
    int tx = threadIdx.x, ty = threadIdx.y;
#pragma unroll
    for (int i = 0; i < 32; i += 8)
        t[ty + i][tx] = W[(size_t)(k0 + ty + i) * N + n0 + tx];
    __syncthreads();
#pragma unroll
    for (int i = 0; i < 32; i += 8) {
        float v = t[tx][ty + i];
        __nv_bfloat16 h = __float2bfloat16(v);
        size_t o = (size_t)(n0 + ty + i) * K + k0 + tx;
        hi[o] = h;
        lo[o] = __float2bfloat16(v - __bfloat162float(h));
    }
}

// ---------------------------------------------------------------------------
// Embedding + positional encoding (fp32 x)
// ---------------------------------------------------------------------------
__global__ void embed_kernel(const int* __restrict__ ids,
                             const float* __restrict__ emb,
                             float* __restrict__ x) {
    int row = blockIdx.x;
    int s   = row & (S_ - 1);
    int id  = ids[row];
    const float* e = emb + (size_t)id * D_;
    float* xr = x + (size_t)row * D_;
    const float coef = -9.210340371976184f / (float)D_;
    for (int d = threadIdx.x; d < D_; d += blockDim.x) {
        int d2 = d & ~1;
        float div = expf((float)d2 * coef);
        float ang = (float)s * div;
        float pe  = (d & 1) ? cosf(ang) : sinf(ang);
        xr[d] = e[d] + pe;
    }
}

// ---------------------------------------------------------------------------
// LayerNorm: fp32 in -> bf16 hi/lo out
// ---------------------------------------------------------------------------
__global__ void ln_kernel(const float* __restrict__ x,
                          const float* __restrict__ w,
                          const float* __restrict__ b,
                          __nv_bfloat16* __restrict__ ohi,
                          __nv_bfloat16* __restrict__ olo) {
    __shared__ float red[4];
    int row = blockIdx.x;
    int tid = threadIdx.x;                // 128 threads
    const float* xr = x + (size_t)row * D_;
    float v[4];
#pragma unroll
    for (int i = 0; i < 4; i++) v[i] = xr[tid + 128 * i];

    float s = v[0] + v[1] + v[2] + v[3];
#pragma unroll
    for (int o = 16; o; o >>= 1) s += __shfl_xor_sync(0xffffffffu, s, o);
    if ((tid & 31) == 0) red[tid >> 5] = s;
    __syncthreads();
    float mu = (red[0] + red[1] + red[2] + red[3]) * (1.0f / D_);

    float d2 = 0.f;
#pragma unroll
    for (int i = 0; i < 4; i++) { float t = v[i] - mu; d2 += t * t; }
#pragma unroll
    for (int o = 16; o; o >>= 1) d2 += __shfl_xor_sync(0xffffffffu, d2, o);
    __syncthreads();
    if ((tid & 31) == 0) red[tid >> 5] = d2;
    __syncthreads();
    float var  = (red[0] + red[1] + red[2] + red[3]) * (1.0f / D_);
    float rstd = rsqrtf(var + 1e-5f);

#pragma unroll
    for (int i = 0; i < 4; i++) {
        int d = tid + 128 * i;
        float y = (v[i] - mu) * rstd * w[d] + b[d];
        __nv_bfloat16 h = __float2bfloat16(y);
        size_t o = (size_t)row * D_ + d;
        ohi[o] = h;
        olo[o] = __float2bfloat16(y - __bfloat162float(h));
    }
}

// ---------------------------------------------------------------------------
// HMMA bf16-split GEMM: C[M,N] = A[M,K] @ B^T  (B stored [N,K] bf16 hi/lo)
// D = Ahi*Bhi + Alo*Bhi + Ahi*Blo (fp32 accum via mma.sync m16n8k16).
// CTA tile 128x128, BK=32, 8 warps (2x4), warp tile 64x32.
// SMEM rows padded to 80B -> conflict-free ldmatrix.
// OP: 0=bias, 1=bias+relu, 2=bias+residual. WF32/WSPLIT select outputs.
// ---------------------------------------------------------------------------
#define BM 128
#define BN 128
#define BK 32
#define AROW 80                          // 32 bf16 = 64B, padded to 80
#define TILE_SM (128 * AROW)             // 10240 B per tile
#define STAGE_SM (4 * TILE_SM)           // Ahi, Alo, Bhi, Blo
#define GEMM_SMEM (2 * STAGE_SM)         // 81920 B, double buffered

template<int OP, bool WF32, bool WSPLIT>
__global__ __launch_bounds__(256, 1)
void gemm_hmma(const __nv_bfloat16* __restrict__ Ahi,
               const __nv_bfloat16* __restrict__ Alo,
               const __nv_bfloat16* __restrict__ Bhi,
               const __nv_bfloat16* __restrict__ Blo,
               const float* __restrict__ bias,
               const float* __restrict__ res,
               float* __restrict__ Cf,
               __nv_bfloat16* __restrict__ Chi,
               __nv_bfloat16* __restrict__ Clo,
               int M, int N, int K) {
    extern __shared__ char smem[];
    int tid = threadIdx.x, lane = tid & 31, wid = tid >> 5;
    int wm = wid & 1, wn = wid >> 1;        // warps: 2 (M) x 4 (N)
    int n0 = blockIdx.x * BN, m0 = blockIdx.y * BM;

    float acc[4][4][4];
#pragma unroll
    for (int i = 0; i < 4; i++)
#pragma unroll
        for (int j = 0; j < 4; j++)
#pragma unroll
            for (int r = 0; r < 4; r++) acc[i][j][r] = 0.f;

    const __nv_bfloat16* baseP[4] = {
        Ahi + (size_t)m0 * K, Alo + (size_t)m0 * K,
        Bhi + (size_t)n0 * K, Blo + (size_t)n0 * K };

    int rowA = tid >> 2;        // 0..63 (+64 for second half)
    int unit = tid & 3;         // 16B unit within 64B row

    // ldmatrix lane addressing (standard m16k16 / n16k16 x4 pattern)
    int mLane = wm * 64 + (lane & 7) + ((lane >> 3) & 1) * 8;
    int nLane = wn * 32 + (lane & 7) + ((lane >> 3) & 1) * 8;
    int kLane = ((lane >> 4) & 1) * 8;

    const int NC = K >> 5;
    uint4 ld[8];

    // Preload chunk 0
#pragma unroll
    for (int t = 0; t < 4; t++)
#pragma unroll
        for (int i = 0; i < 2; i++)
            ld[t * 2 + i] = *(const uint4*)(baseP[t] + (size_t)(rowA + i * 64) * K + unit * 8);
#pragma unroll
    for (int t = 0; t < 4; t++)
#pragma unroll
        for (int i = 0; i < 2; i++)
            *(uint4*)(smem + t * TILE_SM + (rowA + i * 64) * AROW + unit * 16) = ld[t * 2 + i];
    __syncthreads();

    for (int c = 0; c < NC; c++) {
        char* cur = smem + (c & 1) * STAGE_SM;
        char* nxt = smem + ((c + 1) & 1) * STAGE_SM;

        if (c + 1 < NC) {
            int k0 = (c + 1) << 5;
#pragma unroll
            for (int t = 0; t < 4; t++)
#pragma unroll
                for (int i = 0; i < 2; i++)
                    ld[t * 2 + i] = *(const uint4*)(baseP[t] + (size_t)(rowA + i * 64) * K + k0 + unit * 8);
        }

        uint32_t sb = smem_u32(cur);
#pragma unroll
        for (int ks = 0; ks < 2; ks++) {
            int kk = ks * 16 + kLane;
            uint32_t Ah[4][4], Al[4][4], Bh[2][4], Bl[2][4];
#pragma unroll
            for (int mi = 0; mi < 4; mi++) {
                uint32_t a = sb + (mLane + mi * 16) * AROW + kk * 2;
                ldsm4(Ah[mi][0], Ah[mi][1], Ah[mi][2], Ah[mi][3], a);
                ldsm4(Al[mi][0], Al[mi][1], Al[mi][2], Al[mi][3], a + TILE_SM);
            }
#pragma unroll
            for (int pj = 0; pj < 2; pj++) {
                uint32_t a = sb + 2 * TILE_SM + (nLane + pj * 16) * AROW + kk * 2;
                ldsm4(Bh[pj][0], Bh[pj][1], Bh[pj][2], Bh[pj][3], a);
                ldsm4(Bl[pj][0], Bl[pj][1], Bl[pj][2], Bl[pj][3], a + TILE_SM);
            }
#pragma unroll
            for (int mi = 0; mi < 4; mi++)
#pragma unroll
                for (int nj = 0; nj < 4; nj++) {
                    int pj = nj >> 1, h = nj & 1;
                    mma16816(acc[mi][nj], Ah[mi][0], Ah[mi][1], Ah[mi][2], Ah[mi][3],
                             Bh[pj][h], Bh[pj][h + 2]);
                    mma16816(acc[mi][nj], Al[mi][0], Al[mi][1], Al[mi][2], Al[mi][3],
                             Bh[pj][h], Bh[pj][h + 2]);
                    mma16816(acc[mi][nj], Ah[mi][0], Ah[mi][1], Ah[mi][2], Ah[mi][3],
                             Bl[pj][h], Bl[pj][h + 2]);
                }
        }
        __syncthreads();
        if (c + 1 < NC) {
#pragma unroll
            for (int t = 0; t < 4; t++)
#pragma unroll
                for (int i = 0; i < 2; i++)
                    *(uint4*)(nxt + t * TILE_SM + (rowA + i * 64) * AROW + unit * 16) = ld[t * 2 + i];
            __syncthreads();
        }
    }

    // Epilogue: accum fragment layout -> (row g / g+8, cols 2t, 2t+1)
    int g = lane >> 2, t4 = lane & 3;
#pragma unroll
    for (int mi = 0; mi < 4; mi++) {
        int rbase = m0 + wm * 64 + mi * 16 + g;
#pragma unroll
        for (int nj = 0; nj < 4; nj++) {
            int ccol = n0 + wn * 32 + nj * 8 + t4 * 2;
            float2 bv = *(const float2*)(bias + ccol);
#pragma unroll
            for (int rr = 0; rr < 2; rr++) {
                int m = rbase + rr * 8;
                float v0 = acc[mi][nj][rr * 2 + 0] + bv.x;
                float v1 = acc[mi][nj][rr * 2 + 1] + bv.y;
                if (OP == 1) { v0 = fmaxf(v0, 0.f); v1 = fmaxf(v1, 0.f); }
                if (OP == 2) {
                    float2 rv = *(const float2*)(res + (size_t)m * N + ccol);
                    v0 += rv.x; v1 += rv.y;
                }
                if (WF32)
                    *(float2*)(Cf + (size_t)m * N + ccol) = make_float2(v0, v1);
                if (WSPLIT) {
                    __nv_bfloat16 h0 = __float2bfloat16(v0);
                    __nv_bfloat16 h1 = __float2bfloat16(v1);
                    size_t o = (size_t)m * N + ccol;
                    *(__nv_bfloat162*)(Chi + o) = __nv_bfloat162(h0, h1);
                    *(__nv_bfloat162*)(Clo + o) = __nv_bfloat162(
                        __float2bfloat16(v0 - __bfloat162float(h0)),
                        __float2bfloat16(v1 - __bfloat162float(h1)));
                }
            }
        }
    }
}

// ---------------------------------------------------------------------------
// Flash attention (causal + pad mask), fp32 math, DK=64; output split bf16
// ---------------------------------------------------------------------------
#define SP 68
#define FLASH_SMEM ((4 * 64 * SP + 64) * (int)sizeof(float))

__global__ void flash_kernel(const float* __restrict__ Q,
                             const float* __restrict__ K,
                             const float* __restrict__ V,
                             const int* __restrict__ ids,
                             __nv_bfloat16* __restrict__ Ohi,
                             __nv_bfloat16* __restrict__ Olo) {
    extern __shared__ float sm[];
    float* Qs    = sm;
    float* Ks    = Qs + 64 * SP;
    float* Vs    = Ks + 64 * SP;
    float* Ps    = Vs + 64 * SP;
    float* kbias = Ps + 64 * SP;

    int qt = blockIdx.x;
    int h  = blockIdx.y;
    int b  = blockIdx.z;
    int q0 = qt * 64;
    int tid = threadIdx.x;
    int i = tid >> 2;
    int g = tid & 3;

    size_t base = ((size_t)b * S_) * D_ + (size_t)h * DK_;
    const int* idrow = ids + b * S_;
    const float scale = 0.125f;

#pragma unroll
    for (int t = 0; t < 4; t++) {
        int li = tid + t * 256;
        int r  = li >> 4;
        int c4 = (li & 15) << 2;
        *(float4*)(Qs + r * SP + c4) =
            *(const float4*)(Q + base + (size_t)(q0 + r) * D_ + c4);
    }

    float m = -1e30f, lsum = 0.f;
    float o[16];
#pragma unroll
    for (int d = 0; d < 16; d++) o[d] = 0.f;

    for (int k0 = 0; k0 <= q0; k0 += 64) {
#pragma unroll
        for (int t = 0; t < 4; t++) {
            int li = tid + t * 256;
            int r  = li >> 4;
            int c4 = (li & 15) << 2;
            *(float4*)(Ks + r * SP + c4) =
                *(const float4*)(K + base + (size_t)(k0 + r) * D_ + c4);
            *(float4*)(Vs + r * SP + c4) =
                *(const float4*)(V + base + (size_t)(k0 + r) * D_ + c4);
        }
        if (tid < 64) kbias[tid] = (idrow[k0 + tid] != 0) ? 0.f : -1e30f;
        __syncthreads();

        float sc[16];
        float rowmax = -1e30f;
#pragma unroll
        for (int jj = 0; jj < 16; jj++) {
            int j = g + (jj << 2);
            float s = 0.f;
            const float* qr = Qs + i * SP;
            const float* kr = Ks + j * SP;
#pragma unroll
            for (int d = 0; d < 64; d++) s = fmaf(qr[d], kr[d], s);
            s = s * scale + kbias[j];
            if (k0 + j > q0 + i) s = -1e30f;
            sc[jj] = s;
            rowmax = fmaxf(rowmax, s);
        }
        rowmax = fmaxf(rowmax, __shfl_xor_sync(0xffffffffu, rowmax, 1));
        rowmax = fmaxf(rowmax, __shfl_xor_sync(0xffffffffu, rowmax, 2));

        float mnew = fmaxf(m, rowmax);
        float corr = __expf(m - mnew);
        float psum = 0.f;
#pragma unroll
        for (int jj = 0; jj < 16; jj++) {
            float p = __expf(sc[jj] - mnew);
            Ps[i * SP + g + (jj << 2)] = p;
            psum += p;
        }
        psum += __shfl_xor_sync(0xffffffffu, psum, 1);
        psum += __shfl_xor_sync(0xffffffffu, psum, 2);
        lsum = lsum * corr + psum;
        m = mnew;
        __syncwarp();

#pragma unroll
        for (int d = 0; d < 16; d++) o[d] *= corr;
#pragma unroll
        for (int j = 0; j < 64; j++) {
            float p = Ps[i * SP + j];
            const float* vr = Vs + j * SP;
#pragma unroll
            for (int d = 0; d < 16; d++)
                o[d] = fmaf(p, vr[g + (d << 2)], o[d]);
        }
        __syncthreads();
    }

    float inv = 1.f / lsum;
    size_t orow = base + (size_t)(q0 + i) * D_;
#pragma unroll
    for (int d = 0; d < 16; d++) {
        float val = o[d] * inv;
        __nv_bfloat16 hv = __float2bfloat16(val);
        Ohi[orow + g + (d << 2)] = hv;
        Olo[orow + g + (d << 2)] = __float2bfloat16(val - __bfloat162float(hv));
    }
}

// ---------------------------------------------------------------------------
// Host orchestration (graph-capturable: kernel launches only)
// ---------------------------------------------------------------------------
extern "C" void kernel_launch(void* const* d_in, const int* in_sizes, int n_in,
                              void* d_out, int out_size) {
    (void)in_sizes; (void)n_in; (void)out_size;
    const int*   ids  = (const int*)  d_in[0];
    const float* emb  = (const float*)d_in[1];
    const float* wq   = (const float*)d_in[2];
    const float* bq   = (const float*)d_in[3];
    const float* wk   = (const float*)d_in[4];
    const float* bk   = (const float*)d_in[5];
    const float* wv   = (const float*)d_in[6];
    const float* bv   = (const float*)d_in[7];
    const float* wo   = (const float*)d_in[8];
    const float* bo   = (const float*)d_in[9];
    const float* ln1w = (const float*)d_in[10];
    const float* ln1b = (const float*)d_in[11];
    const float* ln2w = (const float*)d_in[12];
    const float* ln2b = (const float*)d_in[13];
    const float* w1   = (const float*)d_in[14];
    const float* b1   = (const float*)d_in[15];
    const float* w2   = (const float*)d_in[16];
    const float* b2   = (const float*)d_in[17];
    const float* outw = (const float*)d_in[18];
    const float* outb = (const float*)d_in[19];
    float* logits = (float*)d_out;

    float *x, *q, *k, *v;
    __nv_bfloat16 *hhi, *hlo, *ohi, *olo, *xhi, *xlo, *fhi, *flo, *whi, *wlo;
    cudaGetSymbolAddress((void**)&x,   g_x);
    cudaGetSymbolAddress((void**)&q,   g_q);
    cudaGetSymbolAddress((void**)&k,   g_k);
    cudaGetSymbolAddress((void**)&v,   g_v);
    cudaGetSymbolAddress((void**)&hhi, g_h_hi);
    cudaGetSymbolAddress((void**)&hlo, g_h_lo);
    cudaGetSymbolAddress((void**)&ohi, g_o_hi);
    cudaGetSymbolAddress((void**)&olo, g_o_lo);
    cudaGetSymbolAddress((void**)&xhi, g_x_hi);
    cudaGetSymbolAddress((void**)&xlo, g_x_lo);
    cudaGetSymbolAddress((void**)&fhi, g_ff_hi);
    cudaGetSymbolAddress((void**)&flo, g_ff_lo);
    cudaGetSymbolAddress((void**)&whi, g_wT_hi);
    cudaGetSymbolAddress((void**)&wlo, g_wT_lo);

    cudaFuncSetAttribute(flash_kernel,
                         cudaFuncAttributeMaxDynamicSharedMemorySize, FLASH_SMEM);
    cudaFuncSetAttribute(gemm_hmma<0,true,false>,
                         cudaFuncAttributeMaxDynamicSharedMemorySize, GEMM_SMEM);
    cudaFuncSetAttribute(gemm_hmma<1,false,true>,
                         cudaFuncAttributeMaxDynamicSharedMemorySize, GEMM_SMEM);
    cudaFuncSetAttribute(gemm_hmma<2,true,true>,
                         cudaFuncAttributeMaxDynamicSharedMemorySize, GEMM_SMEM);

    // Weight prep (transpose + bf16 split)
    dim3 tb(32, 8);
    for (int l = 0; l < L_; l++) {
        prep_w<<<dim3(D_/32, D_/32), tb>>>(wq + (size_t)l*DD, D_, D_, whi + OFF_WQ + (size_t)l*DD, wlo + OFF_WQ + (size_t)l*DD);
        prep_w<<<dim3(D_/32, D_/32), tb>>>(wk + (size_t)l*DD, D_, D_, whi + OFF_WK + (size_t)l*DD, wlo + OFF_WK + (size_t)l*DD);
        prep_w<<<dim3(D_/32, D_/32), tb>>>(wv + (size_t)l*DD, D_, D_, whi + OFF_WV + (size_t)l*DD, wlo + OFF_WV + (size_t)l*DD);
        prep_w<<<dim3(D_/32, D_/32), tb>>>(wo + (size_t)l*DD, D_, D_, whi + OFF_WO + (size_t)l*DD, wlo + OFF_WO + (size_t)l*DD);
        prep_w<<<dim3(DFF_/32, D_/32), tb>>>(w1 + (size_t)l*DF, D_, DFF_, whi + OFF_W1 + (size_t)l*DF, wlo + OFF_W1 + (size_t)l*DF);
        prep_w<<<dim3(D_/32, DFF_/32), tb>>>(w2 + (size_t)l*DF, DFF_, D_, whi + OFF_W2 + (size_t)l*DF, wlo + OFF_W2 + (size_t)l*DF);
    }
    prep_w<<<dim3(V_/32, D_/32), tb>>>(outw, D_, V_, whi + OFF_OW, wlo + OFF_OW);

    embed_kernel<<<M_, 128>>>(ids, emb, x);

    dim3 gD(D_/BN,   M_/BM);    // 4 x 32
    dim3 gF(DFF_/BN, M_/BM);    // 16 x 32
    dim3 gV(V_/BN,   M_/BM);    // 8 x 32
    dim3 gAtt(S_/64, H_, B_);

    for (int l = 0; l < L_; l++) {
        const size_t oDD = (size_t)l * DD;
        const size_t oDF = (size_t)l * DF;

        ln_kernel<<<M_, 128>>>(x, ln1w + l*D_, ln1b + l*D_, hhi, hlo);
        gemm_hmma<0,true,false><<<gD, 256, GEMM_SMEM>>>(hhi, hlo, whi+OFF_WQ+oDD, wlo+OFF_WQ+oDD,
            bq + l*D_, nullptr, q, nullptr, nullptr, M_, D_, D_);
        gemm_hmma<0,true,false><<<gD, 256, GEMM_SMEM>>>(hhi, hlo, whi+OFF_WK+oDD, wlo+OFF_WK+oDD,
            bk + l*D_, nullptr, k, nullptr, nullptr, M_, D_, D_);
        gemm_hmma<0,true,false><<<gD, 256, GEMM_SMEM>>>(hhi, hlo, whi+OFF_WV+oDD, wlo+OFF_WV+oDD,
            bv + l*D_, nullptr, v, nullptr, nullptr, M_, D_, D_);

        flash_kernel<<<gAtt, 256, FLASH_SMEM>>>(q, k, v, ids, ohi, olo);

        // x = o @ wo + bo (no residual — faithful)
        gemm_hmma<0,true,false><<<gD, 256, GEMM_SMEM>>>(ohi, olo, whi+OFF_WO+oDD, wlo+OFF_WO+oDD,
            bo + l*D_, nullptr, x, nullptr, nullptr, M_, D_, D_);

        ln_kernel<<<M_, 128>>>(x, ln2w + l*D_, ln2b + l*D_, hhi, hlo);
        gemm_hmma<1,false,true><<<gF, 256, GEMM_SMEM>>>(hhi, hlo, whi+OFF_W1+oDF, wlo+OFF_W1+oDF,
            b1 + l*DFF_, nullptr, nullptr, fhi, flo, M_, DFF_, D_);
        // x = x + ff @ w2 + b2 ; also emit split for next LN / final logits GEMM
        gemm_hmma<2,true,true><<<gD, 256, GEMM_SMEM>>>(fhi, flo, whi+OFF_W2+oDF, wlo+OFF_W2+oDF,
            b2 + l*D_, x, x, xhi, xlo, M_, D_, DFF_);
    }

    gemm_hmma<0,true,false><<<gV, 256, GEMM_SMEM>>>(xhi, xlo, whi+OFF_OW, wlo+OFF_OW,
        outb, nullptr, logits, nullptr, nullptr, M_, V_, D_);
}